// round 7
// baseline (speedup 1.0000x reference)
#include <cuda_runtime.h>

#define SEQL 20
#define EMB  20
#define NMAX 671744
#define EMAX 4000000
#define NBATCH 8192
#define HID  300
#define NC   22
#define LAT  1640   // 82*20

// ---------------- scratch (static device globals; no runtime alloc) -------
__device__ int   g_deg[NMAX];
__device__ float g_dinv[NMAX];
__device__ __align__(16) float g_hs[(size_t)NMAX * EMB];   // features / latent
__device__ __align__(16) float g_agg[(size_t)NMAX * EMB];  // aggregation buffer
__device__ __align__(16) float g_fc1[(size_t)NBATCH * HID];
__device__ int   g_is64;

// ---------------- helpers -------------------------------------------------
__device__ __forceinline__ unsigned long long fma2(unsigned long long a,
                                                   unsigned long long b,
                                                   unsigned long long c) {
    unsigned long long d;
    asm("fma.rn.f32x2 %0, %1, %2, %3;" : "=l"(d) : "l"(a), "l"(b), "l"(c));
    return d;
}
__device__ __forceinline__ float2 unpack2(unsigned long long v) {
    float x, y;
    asm("mov.b64 {%0, %1}, %2;" : "=f"(x), "=f"(y) : "l"(v));
    return make_float2(x, y);
}
__device__ __forceinline__ void red_add_v4(float* p, float4 v) {
    asm volatile("red.global.add.v4.f32 [%0], {%1,%2,%3,%4};"
                 :: "l"(p), "f"(v.x), "f"(v.y), "f"(v.z), "f"(v.w) : "memory");
}

// ---- launch 1: dtype detect + deg := 1 (self loop) -----------------------
__global__ void k_init(const int* __restrict__ ei32, int n) {
    int i = blockIdx.x * blockDim.x + threadIdx.x;
    if (i < n) g_deg[i] = 1;
    if (blockIdx.x == 0 && threadIdx.x == 0) {
        int all0 = 1;
        for (int q = 1; q < 257; q += 2)
            if (ei32[q] != 0) { all0 = 0; break; }
        g_is64 = all0;   // int64 little-endian: high words of small values are 0
    }
}

// ---- launch 2: degree count ----------------------------------------------
__global__ void k_deg(const void* __restrict__ eiv, int E) {
    int e = blockIdx.x * blockDim.x + threadIdx.x;
    if (e >= E) return;
    int d;
    if (g_is64) d = (int)((const long long*)eiv)[(size_t)E + e];
    else        d = ((const int*)eiv)[E + e];
    atomicAdd(&g_deg[d], 1);
}

// ---- launch 3: layer 1: hs = (x @ W1) * dinv ; agg = hs (self seed) ------
__global__ __launch_bounds__(256) void k_layer1(const float* __restrict__ x,
                                                const float* __restrict__ W,
                                                int n) {
    __shared__ __align__(16) float sW[SEQL * EMB];
    for (int t = threadIdx.x; t < SEQL * EMB; t += 256) sW[t] = W[t];
    __syncthreads();
    int i = blockIdx.x * 256 + threadIdx.x;
    if (i >= n) return;
    float dinv = rsqrtf((float)g_deg[i]);
    g_dinv[i] = dinv;
    float xi[SEQL];
    const float4* xp = (const float4*)(x + (size_t)i * SEQL);
#pragma unroll
    for (int q = 0; q < SEQL / 4; q++) {
        float4 v = __ldg(xp + q);
        xi[4*q] = v.x; xi[4*q+1] = v.y; xi[4*q+2] = v.z; xi[4*q+3] = v.w;
    }
    float o[EMB];
#pragma unroll
    for (int j = 0; j < EMB; j++) o[j] = 0.f;
#pragma unroll
    for (int k = 0; k < SEQL; k++) {
        float xk = xi[k];
#pragma unroll
        for (int q = 0; q < EMB / 4; q++) {
            float4 w = *(const float4*)&sW[k * EMB + 4 * q];
            o[4*q]   = fmaf(xk, w.x, o[4*q]);
            o[4*q+1] = fmaf(xk, w.y, o[4*q+1]);
            o[4*q+2] = fmaf(xk, w.z, o[4*q+2]);
            o[4*q+3] = fmaf(xk, w.w, o[4*q+3]);
        }
    }
    float4* hp = (float4*)(g_hs  + (size_t)i * EMB);
    float4* ap = (float4*)(g_agg + (size_t)i * EMB);
#pragma unroll
    for (int q = 0; q < EMB / 4; q++) {
        float4 v = make_float4(o[4*q]*dinv, o[4*q+1]*dinv, o[4*q+2]*dinv, o[4*q+3]*dinv);
        hp[q] = v; ap[q] = v;
    }
}

// ---- launch 4 (ncu-captured): scatter agg[dst] += hs[src] ----------------
__global__ __launch_bounds__(256) void k_scatter(const void* __restrict__ eiv,
                                                 int E) {
    int e = blockIdx.x * 256 + threadIdx.x;
    if (e >= E) return;
    int s, d;
    if (g_is64) {
        const long long* p = (const long long*)eiv;
        s = (int)p[e];
        d = (int)p[(size_t)E + e];
    } else {
        const int* p = (const int*)eiv;
        s = p[e];
        d = p[E + e];
    }
    const float4* hp = (const float4*)(g_hs + (size_t)s * EMB);
    float* ap = g_agg + (size_t)d * EMB;
#pragma unroll
    for (int q = 0; q < EMB / 4; q++) {
        float4 v = __ldg(hp + q);
        red_add_v4(ap + 4 * q, v);
    }
}

// ---- layer 2: t=relu(agg*dinv+b1); o=(t@W2)*dinv; hs=o; agg=o ------------
__global__ __launch_bounds__(256) void k_layer2(const float* __restrict__ b1,
                                                const float* __restrict__ W,
                                                int n) {
    __shared__ __align__(16) float sW[EMB * EMB];
    __shared__ float sb[EMB];
    for (int t = threadIdx.x; t < EMB * EMB; t += 256) sW[t] = W[t];
    if (threadIdx.x < EMB) sb[threadIdx.x] = b1[threadIdx.x];
    __syncthreads();
    int i = blockIdx.x * 256 + threadIdx.x;
    if (i >= n) return;
    float dinv = g_dinv[i];
    float ti[EMB];
    const float4* ap_in = (const float4*)(g_agg + (size_t)i * EMB);
#pragma unroll
    for (int q = 0; q < EMB / 4; q++) {
        float4 v = ap_in[q];
        ti[4*q]   = fmaxf(fmaf(v.x, dinv, sb[4*q]),   0.f);
        ti[4*q+1] = fmaxf(fmaf(v.y, dinv, sb[4*q+1]), 0.f);
        ti[4*q+2] = fmaxf(fmaf(v.z, dinv, sb[4*q+2]), 0.f);
        ti[4*q+3] = fmaxf(fmaf(v.w, dinv, sb[4*q+3]), 0.f);
    }
    float o[EMB];
#pragma unroll
    for (int j = 0; j < EMB; j++) o[j] = 0.f;
#pragma unroll
    for (int k = 0; k < EMB; k++) {
        float tk = ti[k];
#pragma unroll
        for (int q = 0; q < EMB / 4; q++) {
            float4 w = *(const float4*)&sW[k * EMB + 4 * q];
            o[4*q]   = fmaf(tk, w.x, o[4*q]);
            o[4*q+1] = fmaf(tk, w.y, o[4*q+1]);
            o[4*q+2] = fmaf(tk, w.z, o[4*q+2]);
            o[4*q+3] = fmaf(tk, w.w, o[4*q+3]);
        }
    }
    float4* hp = (float4*)(g_hs  + (size_t)i * EMB);
    float4* ap = (float4*)(g_agg + (size_t)i * EMB);
#pragma unroll
    for (int q = 0; q < EMB / 4; q++) {
        float4 v = make_float4(o[4*q]*dinv, o[4*q+1]*dinv, o[4*q+2]*dinv, o[4*q+3]*dinv);
        hp[q] = v; ap[q] = v;
    }
}

// ---- final: latent(g_hs) = relu(agg*dinv + b2) ---------------------------
__global__ __launch_bounds__(256) void k_final(const float* __restrict__ b2, int n) {
    __shared__ float sb[EMB];
    if (threadIdx.x < EMB) sb[threadIdx.x] = b2[threadIdx.x];
    __syncthreads();
    int i = blockIdx.x * 256 + threadIdx.x;
    if (i >= n) return;
    float dinv = g_dinv[i];
    const float4* ap = (const float4*)(g_agg + (size_t)i * EMB);
    float4* hp = (float4*)(g_hs + (size_t)i * EMB);
#pragma unroll
    for (int q = 0; q < EMB / 4; q++) {
        float4 v = ap[q];
        v.x = fmaxf(fmaf(v.x, dinv, sb[4*q]),   0.f);
        v.y = fmaxf(fmaf(v.y, dinv, sb[4*q+1]), 0.f);
        v.z = fmaxf(fmaf(v.z, dinv, sb[4*q+2]), 0.f);
        v.w = fmaxf(fmaf(v.w, dinv, sb[4*q+3]), 0.f);
        hp[q] = v;
    }
}

// ---------------- fc1 GEMM: relu(latent[8192,1640] @ Wf[1640,300] + bf) ---
// latent lives in g_hs. BM=128 BN=64 BK=8, 256 thr, TM=8 TN=4; pair-packed A
// + duplicated B in smem so the hot loop is pure LDS.128 + fma.f32x2.
#define BM 128
#define BN 64
#define BK 8
__global__ __launch_bounds__(256) void k_fc1(const float* __restrict__ Wf,
                                             const float* __restrict__ bf) {
    __shared__ __align__(16) float As[BK][BM + 4];
    __shared__ __align__(16) float Bsd[BK][2 * BN + 4];
    const int tid  = threadIdx.x;
    const int row0 = blockIdx.x * BM;
    const int col0 = blockIdx.y * BN;
    const int tm = (tid >> 4) * 8;      // 0..120
    const int tn = (tid & 15) * 4;      // 0..60
    const int arow = tid >> 1;          // 0..127
    const int ak   = (tid & 1) * 4;     // 0 or 4
    const int brow = tid >> 4;          // 0..7 (tid<128)
    const int bc   = (tid & 15) * 4;    // 0..60

    unsigned long long acc[4][4];       // [m-pair][col]
#pragma unroll
    for (int p = 0; p < 4; p++)
#pragma unroll
        for (int q = 0; q < 4; q++) acc[p][q] = 0ULL;

    for (int k0 = 0; k0 < LAT; k0 += BK) {
        float4 va = *(const float4*)(g_hs + (size_t)(row0 + arow) * LAT + (k0 + ak));
        As[ak + 0][arow] = va.x;
        As[ak + 1][arow] = va.y;
        As[ak + 2][arow] = va.z;
        As[ak + 3][arow] = va.w;
        if (tid < 128) {
            int gc = col0 + bc;
            float4 vb = make_float4(0.f, 0.f, 0.f, 0.f);
            if (gc < HID)
                vb = *(const float4*)(Wf + (size_t)(k0 + brow) * HID + gc);
            // duplicated pairs {x,x,y,y,z,z,w,w}
            *(float4*)&Bsd[brow][2 * bc]     = make_float4(vb.x, vb.x, vb.y, vb.y);
            *(float4*)&Bsd[brow][2 * bc + 4] = make_float4(vb.z, vb.z, vb.w, vb.w);
        }
        __syncthreads();
#pragma unroll
        for (int k = 0; k < BK; k++) {
            ulonglong2 a01 = *(const ulonglong2*)&As[k][tm];
            ulonglong2 a23 = *(const ulonglong2*)&As[k][tm + 4];
            ulonglong2 b01 = *(const ulonglong2*)&Bsd[k][2 * tn];
            ulonglong2 b23 = *(const ulonglong2*)&Bsd[k][2 * tn + 4];
            acc[0][0] = fma2(a01.x, b01.x, acc[0][0]);
            acc[0][1] = fma2(a01.x, b01.y, acc[0][1]);
            acc[0][2] = fma2(a01.x, b23.x, acc[0][2]);
            acc[0][3] = fma2(a01.x, b23.y, acc[0][3]);
            acc[1][0] = fma2(a01.y, b01.x, acc[1][0]);
            acc[1][1] = fma2(a01.y, b01.y, acc[1][1]);
            acc[1][2] = fma2(a01.y, b23.x, acc[1][2]);
            acc[1][3] = fma2(a01.y, b23.y, acc[1][3]);
            acc[2][0] = fma2(a23.x, b01.x, acc[2][0]);
            acc[2][1] = fma2(a23.x, b01.y, acc[2][1]);
            acc[2][2] = fma2(a23.x, b23.x, acc[2][2]);
            acc[2][3] = fma2(a23.x, b23.y, acc[2][3]);
            acc[3][0] = fma2(a23.y, b01.x, acc[3][0]);
            acc[3][1] = fma2(a23.y, b01.y, acc[3][1]);
            acc[3][2] = fma2(a23.y, b23.x, acc[3][2]);
            acc[3][3] = fma2(a23.y, b23.y, acc[3][3]);
        }
        __syncthreads();
    }
    int gc = col0 + tn;
    if (gc < HID) {   // HID%4==0 so the whole float4 is valid
        float bb[4];
#pragma unroll
        for (int q = 0; q < 4; q++) bb[q] = bf[gc + q];
#pragma unroll
        for (int p = 0; p < 4; p++) {
            float2 u0 = unpack2(acc[p][0]);
            float2 u1 = unpack2(acc[p][1]);
            float2 u2 = unpack2(acc[p][2]);
            float2 u3 = unpack2(acc[p][3]);
            int r = row0 + tm + 2 * p;
            float4 vlo = make_float4(fmaxf(u0.x + bb[0], 0.f), fmaxf(u1.x + bb[1], 0.f),
                                     fmaxf(u2.x + bb[2], 0.f), fmaxf(u3.x + bb[3], 0.f));
            float4 vhi = make_float4(fmaxf(u0.y + bb[0], 0.f), fmaxf(u1.y + bb[1], 0.f),
                                     fmaxf(u2.y + bb[2], 0.f), fmaxf(u3.y + bb[3], 0.f));
            *(float4*)(g_fc1 + (size_t)r * HID + gc)       = vlo;
            *(float4*)(g_fc1 + (size_t)(r + 1) * HID + gc) = vhi;
        }
    }
}

// ---------------- out: [8192,300] @ [300,22] + out_b ----------------------
__global__ __launch_bounds__(256) void k_out(const float* __restrict__ Wo,
                                             const float* __restrict__ bo,
                                             float* __restrict__ out) {
    __shared__ float sW[HID * NC];
    __shared__ float sb[NC];
    for (int t = threadIdx.x; t < HID * NC; t += 256) sW[t] = Wo[t];
    if (threadIdx.x < NC) sb[threadIdx.x] = bo[threadIdx.x];
    __syncthreads();
    int w = threadIdx.x >> 5, lane = threadIdx.x & 31;
    int rbase = blockIdx.x * 64 + w * 8;
#pragma unroll 1
    for (int r8 = 0; r8 < 8; r8++) {
        int r = rbase + r8;
        const float4* fr4 = (const float4*)(g_fc1 + (size_t)r * HID);
        if (lane < NC) {
            float accv = 0.f;
#pragma unroll 5
            for (int k4 = 0; k4 < HID / 4; k4++) {
                float4 v = fr4[k4];
                int k = 4 * k4;
                accv = fmaf(v.x, sW[(k + 0) * NC + lane], accv);
                accv = fmaf(v.y, sW[(k + 1) * NC + lane], accv);
                accv = fmaf(v.z, sW[(k + 2) * NC + lane], accv);
                accv = fmaf(v.w, sW[(k + 3) * NC + lane], accv);
            }
            out[(size_t)r * NC + lane] = accv + sb[lane];
        }
    }
}

// ---------------- launch --------------------------------------------------
extern "C" void kernel_launch(void* const* d_in, const int* in_sizes, int n_in,
                              void* d_out, int out_size) {
    const float* x    = (const float*)d_in[0];
    const void*  ei   = d_in[1];
    const float* W1   = (const float*)d_in[3];
    const float* b1   = (const float*)d_in[4];
    const float* W2   = (const float*)d_in[5];
    const float* b2   = (const float*)d_in[6];
    const float* fc1W = (const float*)d_in[7];
    const float* fc1b = (const float*)d_in[8];
    const float* outW = (const float*)d_in[9];
    const float* outb = (const float*)d_in[10];
    float* out = (float*)d_out;

    int N = in_sizes[0] / SEQL;
    int E = in_sizes[1] / 2;
    int rows = out_size / NC;                // 8192
    int nb = (N + 255) / 256;
    int eb = (E + 255) / 256;

    k_init<<<nb, 256>>>((const int*)ei, N);   // 1
    k_deg<<<eb, 256>>>(ei, E);                // 2
    k_layer1<<<nb, 256>>>(x, W1, N);          // 3: -> hs (+ agg seed)
    k_scatter<<<eb, 256>>>(ei, E);            // 4: ncu-captured
    k_layer2<<<nb, 256>>>(b1, W2, N);         // 5
    k_scatter<<<eb, 256>>>(ei, E);            // 6
    k_final<<<nb, 256>>>(b2, N);              // 7: -> hs (latent)
    dim3 gfc(rows / BM, (HID + BN - 1) / BN);
    k_fc1<<<gfc, 256>>>(fc1W, fc1b);          // 8
    k_out<<<rows / 64, 256>>>(outW, outb, out); // 9
}

// round 8
// speedup vs baseline: 1.2932x; 1.2932x over previous
#include <cuda_runtime.h>

#define SEQL 20
#define EMB  20
#define NMAX 671744
#define EMAX 4000000
#define NBATCH 8192
#define HID  300
#define NC   22
#define LAT  1640   // 82*20

// ---------------- scratch (static device globals; no runtime alloc) -------
__device__ int   g_deg[NMAX];
__device__ float g_dinv[NMAX];
__device__ float g_hs[(size_t)NMAX * EMB];    // scaled features / latent
__device__ float g_agg[(size_t)NMAX * EMB];   // aggregation buffer
__device__ int   g_src[EMAX];
__device__ int   g_dst[EMAX];
__device__ float g_fc1[(size_t)NBATCH * HID];
__device__ int   g_is64;

// ---------------- helpers -------------------------------------------------
__device__ __forceinline__ unsigned long long pack2(float a, float b) {
    unsigned long long r;
    asm("mov.b64 %0, {%1, %2};" : "=l"(r)
        : "r"(__float_as_uint(a)), "r"(__float_as_uint(b)));
    return r;
}
__device__ __forceinline__ unsigned long long fma2(unsigned long long a,
                                                   unsigned long long b,
                                                   unsigned long long c) {
    unsigned long long d;
    asm("fma.rn.f32x2 %0, %1, %2, %3;" : "=l"(d) : "l"(a), "l"(b), "l"(c));
    return d;
}
__device__ __forceinline__ float2 unpack2(unsigned long long v) {
    float x, y;
    asm("mov.b64 {%0, %1}, %2;" : "=f"(x), "=f"(y) : "l"(v));
    return make_float2(x, y);
}
__device__ __forceinline__ void red_add_v4(float* p, float4 v) {
    asm volatile("red.global.add.v4.f32 [%0], {%1,%2,%3,%4};"
                 :: "l"(p), "f"(v.x), "f"(v.y), "f"(v.z), "f"(v.w) : "memory");
}

// ---- launch 1: dtype detect + deg := 1 (self loop) -----------------------
__global__ void k_init(const int* __restrict__ ei32, int n) {
    int i = blockIdx.x * blockDim.x + threadIdx.x;
    if (i < n) g_deg[i] = 1;           // self loop
    if (blockIdx.x == 0 && threadIdx.x == 0) {
        int all0 = 1;
        for (int q = 1; q < 257; q += 2)
            if (ei32[q] != 0) { all0 = 0; break; }
        g_is64 = all0;   // int64 little-endian: high words of small values are 0
    }
}

// ---- launch 2: stage edges to int32 + degree count -----------------------
__global__ void k_edges_prep(const void* __restrict__ eiv, int E) {
    int e = blockIdx.x * blockDim.x + threadIdx.x;
    if (e >= E) return;
    int s, d;
    if (g_is64) {
        const long long* p = (const long long*)eiv;
        s = (int)p[e];
        d = (int)p[(size_t)E + e];
    } else {
        const int* p = (const int*)eiv;
        s = p[e];
        d = p[E + e];
    }
    g_src[e] = s;
    g_dst[e] = d;
    atomicAdd(&g_deg[d], 1);
}

// ---- launch 3: hs = (x @ W1) * dinv ;  agg = hs (self-loop pre-seed) -----
__global__ __launch_bounds__(256) void k_layer1(const float* __restrict__ x,
                                                const float* __restrict__ W,
                                                int n) {
    __shared__ __align__(16) float sW[SEQL * EMB];
    for (int t = threadIdx.x; t < SEQL * EMB; t += 256) sW[t] = W[t];
    __syncthreads();
    int i = blockIdx.x * 256 + threadIdx.x;
    if (i >= n) return;
    float dinv = rsqrtf((float)g_deg[i]);
    g_dinv[i] = dinv;
    float xi[SEQL];
    const float4* xp = (const float4*)(x + (size_t)i * SEQL);
#pragma unroll
    for (int q = 0; q < SEQL / 4; q++) {
        float4 v = __ldg(xp + q);
        xi[4*q] = v.x; xi[4*q+1] = v.y; xi[4*q+2] = v.z; xi[4*q+3] = v.w;
    }
    float o[EMB];
#pragma unroll
    for (int j = 0; j < EMB; j++) o[j] = 0.f;
#pragma unroll
    for (int k = 0; k < SEQL; k++) {
        float xk = xi[k];
#pragma unroll
        for (int q = 0; q < EMB / 4; q++) {
            float4 w = *(const float4*)&sW[k * EMB + 4 * q];
            o[4*q]   = fmaf(xk, w.x, o[4*q]);
            o[4*q+1] = fmaf(xk, w.y, o[4*q+1]);
            o[4*q+2] = fmaf(xk, w.z, o[4*q+2]);
            o[4*q+3] = fmaf(xk, w.w, o[4*q+3]);
        }
    }
    float4* hp = (float4*)(g_hs  + (size_t)i * EMB);
    float4* ap = (float4*)(g_agg + (size_t)i * EMB);
#pragma unroll
    for (int q = 0; q < EMB / 4; q++) {
        float4 v = make_float4(o[4*q]*dinv, o[4*q+1]*dinv, o[4*q+2]*dinv, o[4*q+3]*dinv);
        hp[q] = v; ap[q] = v;
    }
}

// ---- launch 4 (ncu slot): agg[dst] += hs[src] (staged int32, RED.128 x5) -
__global__ __launch_bounds__(256) void k_scatter(int E) {
    int e = blockIdx.x * blockDim.x + threadIdx.x;
    if (e >= E) return;
    int s = g_src[e], d = g_dst[e];
    const float4* hp = (const float4*)(g_hs + (size_t)s * EMB);
    float* ap = g_agg + (size_t)d * EMB;
#pragma unroll
    for (int q = 0; q < EMB / 4; q++) {
        float4 v = __ldg(hp + q);
        red_add_v4(ap + 4 * q, v);
    }
}

// ---- t = relu(agg*dinv + b1);  o = (t @ W2)*dinv;  hs = o;  agg = o ------
__global__ __launch_bounds__(256) void k_layer2(const float* __restrict__ b1,
                                                const float* __restrict__ W,
                                                int n) {
    __shared__ __align__(16) float sW[EMB * EMB];
    __shared__ float sb[EMB];
    for (int t = threadIdx.x; t < EMB * EMB; t += 256) sW[t] = W[t];
    if (threadIdx.x < EMB) sb[threadIdx.x] = b1[threadIdx.x];
    __syncthreads();
    int i = blockIdx.x * 256 + threadIdx.x;
    if (i >= n) return;
    float dinv = g_dinv[i];
    float ti[EMB];
    const float4* ap_in = (const float4*)(g_agg + (size_t)i * EMB);
#pragma unroll
    for (int q = 0; q < EMB / 4; q++) {
        float4 v = ap_in[q];
        ti[4*q]   = fmaxf(fmaf(v.x, dinv, sb[4*q]),   0.f);
        ti[4*q+1] = fmaxf(fmaf(v.y, dinv, sb[4*q+1]), 0.f);
        ti[4*q+2] = fmaxf(fmaf(v.z, dinv, sb[4*q+2]), 0.f);
        ti[4*q+3] = fmaxf(fmaf(v.w, dinv, sb[4*q+3]), 0.f);
    }
    float o[EMB];
#pragma unroll
    for (int j = 0; j < EMB; j++) o[j] = 0.f;
#pragma unroll
    for (int k = 0; k < EMB; k++) {
        float tk = ti[k];
#pragma unroll
        for (int q = 0; q < EMB / 4; q++) {
            float4 w = *(const float4*)&sW[k * EMB + 4 * q];
            o[4*q]   = fmaf(tk, w.x, o[4*q]);
            o[4*q+1] = fmaf(tk, w.y, o[4*q+1]);
            o[4*q+2] = fmaf(tk, w.z, o[4*q+2]);
            o[4*q+3] = fmaf(tk, w.w, o[4*q+3]);
        }
    }
    float4* hp = (float4*)(g_hs  + (size_t)i * EMB);
    float4* ap = (float4*)(g_agg + (size_t)i * EMB);
#pragma unroll
    for (int q = 0; q < EMB / 4; q++) {
        float4 v = make_float4(o[4*q]*dinv, o[4*q+1]*dinv, o[4*q+2]*dinv, o[4*q+3]*dinv);
        hp[q] = v; ap[q] = v;
    }
}

// ---- latent = relu(agg*dinv + b2)   -> stored into g_hs ------------------
__global__ __launch_bounds__(256) void k_final(const float* __restrict__ b2, int n) {
    __shared__ float sb[EMB];
    if (threadIdx.x < EMB) sb[threadIdx.x] = b2[threadIdx.x];
    __syncthreads();
    int i = blockIdx.x * 256 + threadIdx.x;
    if (i >= n) return;
    float dinv = g_dinv[i];
    const float4* ap = (const float4*)(g_agg + (size_t)i * EMB);
    float4* hp = (float4*)(g_hs + (size_t)i * EMB);
#pragma unroll
    for (int q = 0; q < EMB / 4; q++) {
        float4 v = ap[q];
        v.x = fmaxf(fmaf(v.x, dinv, sb[4*q]),   0.f);
        v.y = fmaxf(fmaf(v.y, dinv, sb[4*q+1]), 0.f);
        v.z = fmaxf(fmaf(v.z, dinv, sb[4*q+2]), 0.f);
        v.w = fmaxf(fmaf(v.w, dinv, sb[4*q+3]), 0.f);
        hp[q] = v;
    }
}

// fc1: C[8192,300] = relu(latent[8192,1640] @ Wf[1640,300] + bf)
// BM=128 BN=64 BK=8, 256 thr, TM=8 TN=4, packed f32x2 FMA (m-pair lanes)
#define BM 128
#define BN 64
#define BK 8
__global__ __launch_bounds__(256) void k_fc1(const float* __restrict__ Wf,
                                             const float* __restrict__ bf) {
    __shared__ __align__(16) float As[BK][BM + 4];
    __shared__ __align__(16) float Bs[BK][BN + 4];
    const int tid  = threadIdx.x;
    const int row0 = blockIdx.x * BM;
    const int col0 = blockIdx.y * BN;
    const int tm = (tid >> 4) * 8;      // 0..120
    const int tn = (tid & 15) * 4;      // 0..60
    const int arow = tid >> 1;          // 0..127
    const int ak   = (tid & 1) * 4;     // 0 or 4
    const int brow = tid >> 4;          // 0..7 (tid<128)
    const int bc   = (tid & 15) * 4;    // 0..60

    unsigned long long acc[4][4];       // [m-pair][col]
#pragma unroll
    for (int p = 0; p < 4; p++)
#pragma unroll
        for (int q = 0; q < 4; q++) acc[p][q] = 0ULL;

    for (int k0 = 0; k0 < LAT; k0 += BK) {
        float4 va = *(const float4*)(g_hs + (size_t)(row0 + arow) * LAT + (k0 + ak));
        As[ak + 0][arow] = va.x;
        As[ak + 1][arow] = va.y;
        As[ak + 2][arow] = va.z;
        As[ak + 3][arow] = va.w;
        if (tid < 128) {
            int gc = col0 + bc;
            float4 vb = make_float4(0.f, 0.f, 0.f, 0.f);
            if (gc < HID)
                vb = *(const float4*)(Wf + (size_t)(k0 + brow) * HID + gc);
            *(float4*)&Bs[brow][bc] = vb;
        }
        __syncthreads();
#pragma unroll
        for (int k = 0; k < BK; k++) {
            float4 a0 = *(const float4*)&As[k][tm];
            float4 a1 = *(const float4*)&As[k][tm + 4];
            float4 bv = *(const float4*)&Bs[k][tn];
            unsigned long long ap0 = pack2(a0.x, a0.y);
            unsigned long long ap1 = pack2(a0.z, a0.w);
            unsigned long long ap2 = pack2(a1.x, a1.y);
            unsigned long long ap3 = pack2(a1.z, a1.w);
            unsigned long long bb0 = pack2(bv.x, bv.x);
            unsigned long long bb1 = pack2(bv.y, bv.y);
            unsigned long long bb2 = pack2(bv.z, bv.z);
            unsigned long long bb3 = pack2(bv.w, bv.w);
            acc[0][0] = fma2(ap0, bb0, acc[0][0]);
            acc[0][1] = fma2(ap0, bb1, acc[0][1]);
            acc[0][2] = fma2(ap0, bb2, acc[0][2]);
            acc[0][3] = fma2(ap0, bb3, acc[0][3]);
            acc[1][0] = fma2(ap1, bb0, acc[1][0]);
            acc[1][1] = fma2(ap1, bb1, acc[1][1]);
            acc[1][2] = fma2(ap1, bb2, acc[1][2]);
            acc[1][3] = fma2(ap1, bb3, acc[1][3]);
            acc[2][0] = fma2(ap2, bb0, acc[2][0]);
            acc[2][1] = fma2(ap2, bb1, acc[2][1]);
            acc[2][2] = fma2(ap2, bb2, acc[2][2]);
            acc[2][3] = fma2(ap2, bb3, acc[2][3]);
            acc[3][0] = fma2(ap3, bb0, acc[3][0]);
            acc[3][1] = fma2(ap3, bb1, acc[3][1]);
            acc[3][2] = fma2(ap3, bb2, acc[3][2]);
            acc[3][3] = fma2(ap3, bb3, acc[3][3]);
        }
        __syncthreads();
    }
    int gc = col0 + tn;
    if (gc < HID) {   // HID%4==0 so the whole float4 is valid
        float bb[4];
#pragma unroll
        for (int q = 0; q < 4; q++) bb[q] = bf[gc + q];
#pragma unroll
        for (int p = 0; p < 4; p++) {
            float2 u0 = unpack2(acc[p][0]);
            float2 u1 = unpack2(acc[p][1]);
            float2 u2 = unpack2(acc[p][2]);
            float2 u3 = unpack2(acc[p][3]);
            int r = row0 + tm + 2 * p;
            float4 vlo = make_float4(fmaxf(u0.x + bb[0], 0.f), fmaxf(u1.x + bb[1], 0.f),
                                     fmaxf(u2.x + bb[2], 0.f), fmaxf(u3.x + bb[3], 0.f));
            float4 vhi = make_float4(fmaxf(u0.y + bb[0], 0.f), fmaxf(u1.y + bb[1], 0.f),
                                     fmaxf(u2.y + bb[2], 0.f), fmaxf(u3.y + bb[3], 0.f));
            *(float4*)(g_fc1 + (size_t)r * HID + gc)       = vlo;
            *(float4*)(g_fc1 + (size_t)(r + 1) * HID + gc) = vhi;
        }
    }
}

// out: [8192,300] @ [300,22] + out_b
__global__ __launch_bounds__(256) void k_out(const float* __restrict__ Wo,
                                             const float* __restrict__ bo,
                                             float* __restrict__ out) {
    __shared__ float sW[HID * NC];
    __shared__ float sb[NC];
    for (int t = threadIdx.x; t < HID * NC; t += 256) sW[t] = Wo[t];
    if (threadIdx.x < NC) sb[threadIdx.x] = bo[threadIdx.x];
    __syncthreads();
    int w = threadIdx.x >> 5, lane = threadIdx.x & 31;
    int rbase = blockIdx.x * 64 + w * 8;
#pragma unroll 1
    for (int r8 = 0; r8 < 8; r8++) {
        int r = rbase + r8;
        const float4* fr4 = (const float4*)(g_fc1 + (size_t)r * HID);
        if (lane < NC) {
            float accv = 0.f;
#pragma unroll 5
            for (int k4 = 0; k4 < HID / 4; k4++) {
                float4 v = fr4[k4];
                int k = 4 * k4;
                accv = fmaf(v.x, sW[(k + 0) * NC + lane], accv);
                accv = fmaf(v.y, sW[(k + 1) * NC + lane], accv);
                accv = fmaf(v.z, sW[(k + 2) * NC + lane], accv);
                accv = fmaf(v.w, sW[(k + 3) * NC + lane], accv);
            }
            out[(size_t)r * NC + lane] = accv + sb[lane];
        }
    }
}

// ---------------- launch --------------------------------------------------
extern "C" void kernel_launch(void* const* d_in, const int* in_sizes, int n_in,
                              void* d_out, int out_size) {
    const float* x    = (const float*)d_in[0];
    const void*  ei   = d_in[1];
    const float* W1   = (const float*)d_in[3];
    const float* b1   = (const float*)d_in[4];
    const float* W2   = (const float*)d_in[5];
    const float* b2   = (const float*)d_in[6];
    const float* fc1W = (const float*)d_in[7];
    const float* fc1b = (const float*)d_in[8];
    const float* outW = (const float*)d_in[9];
    const float* outb = (const float*)d_in[10];
    float* out = (float*)d_out;

    int N = in_sizes[0] / SEQL;
    int E = in_sizes[1] / 2;
    int rows = out_size / NC;                // 8192
    int nb = (N + 255) / 256;
    int eb = (E + 255) / 256;

    k_init<<<nb, 256>>>((const int*)ei, N);     // 1
    k_edges_prep<<<eb, 256>>>(ei, E);           // 2
    k_layer1<<<nb, 256>>>(x, W1, N);            // 3
    k_scatter<<<eb, 256>>>(E);                  // 4  <-- ncu slot
    k_layer2<<<nb, 256>>>(b1, W2, N);           // 5
    k_scatter<<<eb, 256>>>(E);                  // 6
    k_final<<<nb, 256>>>(b2, N);                // 7
    dim3 gfc(rows / BM, (HID + BN - 1) / BN);
    k_fc1<<<gfc, 256>>>(fc1W, fc1b);            // 8
    k_out<<<rows / 64, 256>>>(outW, outb, out); // 9
}